// round 3
// baseline (speedup 1.0000x reference)
#include <cuda_runtime.h>
#include <math.h>

#define TD    30
#define NB    16
#define NAGT  32
#define NC    12
#define NA    512
#define ROWS  6144
#define HID   48
#define NBIN  36
#define KSP   1728

#define OFF_SC   0
#define OFF_DY   (TD*ROWS)
#define OFF_FEAT (OFF_DY + TD*ROWS*2)

#define RBR_F   0.34657359027997264f
#define PI_F    3.14159265358979323846f
#define TWOPI_F 6.28318530717958647692f

__device__ float g_c1[16*16*32*32];
__device__ float g_c2[16*32*32*32];
__device__ float g_featT[16*32*32*32];
__device__ float g_pooled[(long)TD*ROWS*32];
__device__ float g_h[ROWS*HID];
__device__ float g_sp[(long)ROWS*KSP];
__device__ float g_WspT[KSP*HID];
__device__ float g_spp[2*ROWS*HID];

// ---------------- CNN ----------------
__global__ void conv1_kernel(const float* __restrict__ scene,
                             const float* __restrict__ w,
                             const float* __restrict__ bias) {
    __shared__ float sIn[68*68];
    __shared__ float sW[25];
    int b  = blockIdx.x >> 4;
    int oc = blockIdx.x & 15;
    int tid = threadIdx.x;
    float acc[4] = {0.f,0.f,0.f,0.f};
    for (int ic = 0; ic < 3; ic++) {
        if (tid < 25) sW[tid] = w[(oc*3+ic)*25 + tid];
        for (int idx = tid; idx < 68*68; idx += 256) {
            int py = idx / 68, px = idx % 68;
            int iy = py - 2, ix = px - 2;
            float v = 0.f;
            if (iy >= 0 && iy < 64 && ix >= 0 && ix < 64)
                v = scene[((b*3+ic)*64 + iy)*64 + ix];
            sIn[idx] = v;
        }
        __syncthreads();
        #pragma unroll
        for (int p = 0; p < 4; p++) {
            int opix = tid + p*256;
            int oy = opix >> 5, ox = opix & 31;
            float a = 0.f;
            #pragma unroll
            for (int ky = 0; ky < 5; ky++)
                #pragma unroll
                for (int kx = 0; kx < 5; kx++)
                    a += sIn[(oy*2+ky)*68 + ox*2+kx] * sW[ky*5+kx];
            acc[p] += a;
        }
        __syncthreads();
    }
    float bb = bias[oc];
    #pragma unroll
    for (int p = 0; p < 4; p++)
        g_c1[(b*16+oc)*1024 + tid + p*256] = fmaxf(acc[p] + bb, 0.f);
}

__global__ void conv_s1_kernel(const float* __restrict__ w,
                               const float* __restrict__ bias,
                               int IC, int OC, int mode,
                               float* __restrict__ feat_out) {
    __shared__ float sIn[36*36];
    __shared__ float sW[25];
    int b  = blockIdx.x / OC;
    int oc = blockIdx.x % OC;
    int tid = threadIdx.x;
    const float* in = (mode == 2) ? g_c1 : g_c2;
    float acc[4] = {0.f,0.f,0.f,0.f};
    for (int ic = 0; ic < IC; ic++) {
        if (tid < 25) sW[tid] = w[(oc*IC+ic)*25 + tid];
        for (int idx = tid; idx < 1296; idx += 256) {
            int py = idx / 36, px = idx % 36;
            int iy = py - 2, ix = px - 2;
            float v = 0.f;
            if (iy >= 0 && iy < 32 && ix >= 0 && ix < 32)
                v = in[((b*IC+ic)*32 + iy)*32 + ix];
            sIn[idx] = v;
        }
        __syncthreads();
        #pragma unroll
        for (int p = 0; p < 4; p++) {
            int opix = tid + p*256;
            int oy = opix >> 5, ox = opix & 31;
            float a = 0.f;
            #pragma unroll
            for (int ky = 0; ky < 5; ky++)
                #pragma unroll
                for (int kx = 0; kx < 5; kx++)
                    a += sIn[(oy+ky)*36 + ox+kx] * sW[ky*5+kx];
            acc[p] += a;
        }
        __syncthreads();
    }
    float bb = bias[oc];
    #pragma unroll
    for (int p = 0; p < 4; p++) {
        int opix = tid + p*256;
        int oy = opix >> 5, ox = opix & 31;
        float val = fmaxf(acc[p] + bb, 0.f);
        if (mode == 2) {
            g_c2[(b*OC+oc)*1024 + opix] = val;
        } else {
            g_featT[((b*32 + oy)*32 + ox)*32 + oc] = val;
            feat_out[(b*OC+oc)*1024 + opix] = val;
        }
    }
}

// ---------------- scene pooling (all timesteps at once) ----------------
__global__ void pool_kernel(const float* __restrict__ position) {
    int item = (blockIdx.x << 3) + (threadIdx.x >> 5);
    int lane = threadIdx.x & 31;
    if (item >= TD*ROWS) return;
    int r = item % ROWS;
    int a = r / NC;
    int b = a >> 5;
    float p0 = position[(long)item*2 + 0];
    float p1 = position[(long)item*2 + 1];
    float mx = (p0 + 56.0f) * 32.0f / 112.0f + 1.0f;
    float my = (p1 + 56.0f) * 32.0f / 112.0f + 1.0f;
    int xi = (int)fminf(fmaxf(floorf(mx), 0.f), 33.f);
    int yi = (int)fminf(fmaxf(floorf(my), 0.f), 33.f);
    float v = 0.f;
    if (xi >= 1 && xi <= 32 && yi >= 1 && yi <= 32)
        v = g_featT[((b*32 + (yi-1))*32 + (xi-1))*32 + lane];
    g_pooled[(long)item*32 + lane] = v;
}

__global__ void hinit_kernel(const float* __restrict__ Hx) {
    int idx = blockIdx.x*256 + threadIdx.x;
    if (idx >= ROWS*HID) return;
    int a = idx / (NC*HID);
    int d = idx % HID;
    g_h[idx] = Hx[a*HID + d];
}

__global__ void wsp_transpose_kernel(const float* __restrict__ fcsp_w) {
    int idx = blockIdx.x*256 + threadIdx.x;
    if (idx >= KSP*HID) return;
    int k = idx / HID, o = idx % HID;
    g_WspT[idx] = fcsp_w[o*KSP + k];
}

// ---------------- social pooling (per step) ----------------
__global__ void social_kernel(const float* __restrict__ position, int t) {
    __shared__ float px[32], py[32];
    __shared__ float hS[32][48];
    __shared__ int   binS[4][32];
    __shared__ float cntS[4][36];
    __shared__ float sumS[4][KSP];
    int bx = blockIdx.x;
    int e   = bx / 96;
    int rem = bx % 96;
    int c   = rem / 8;
    int q   = rem % 8;
    int tid = threadIdx.x;
    int wid = tid >> 5, lane = tid & 31;

    if (tid < 32) {
        long off = (((long)t*NA + e*32 + tid)*NC + c)*2;
        px[tid] = position[off];
        py[tid] = position[off+1];
    }
    for (int idx = tid; idx < 32*48; idx += 128) {
        int j = idx / 48, d = idx % 48;
        hS[j][d] = g_h[((e*32 + j)*NC + c)*48 + d];
    }
    for (int idx = tid; idx < 4*36; idx += 128) cntS[idx/36][idx%36] = 0.f;
    for (int idx = tid; idx < 4*KSP; idx += 128) sumS[idx/KSP][idx%KSP] = 0.f;
    __syncthreads();

    {
        int il = wid;
        int j  = lane;
        int i  = q*4 + il;
        float xd = px[i] - px[j];
        float yd = py[i] - py[j];
        float dist = sqrtf(xd*xd + yd*yd);
        float rf = floorf(logf(dist * 2.0f + 1e-6f) / RBR_F);
        int bin = -1;
        if (rf >= 0.0f && rf < 6.0f) {
            float tt = atan2f(yd, xd) + PI_F - 1e-6f;
            int wg = (int)floorf(tt / TWOPI_F * 6.0f);
            wg = max(0, min(5, wg));
            bin = (int)rf * 6 + wg;
            atomicAdd(&cntS[il][bin], 1.0f);
        }
        binS[il][j] = bin;
    }
    __syncthreads();

    for (int j = 0; j < 32; j++) {
        int b = binS[wid][j];
        if (b < 0) continue;
        sumS[wid][b*48 + lane] += hS[j][lane];
        if (lane < 16) sumS[wid][b*48 + 32 + lane] += hS[j][32 + lane];
    }
    __syncthreads();
    for (int idx = tid; idx < 4*36; idx += 128) {
        float cv = cntS[idx/36][idx%36];
        cntS[idx/36][idx%36] = 1.0f / fmaxf(cv, 1.0f);
    }
    __syncthreads();
    for (int idx = tid; idx < 4*432; idx += 128) {
        int il = idx / 432;
        int k4 = idx % 432;
        float inv = cntS[il][k4/12];
        float4 s = *(float4*)&sumS[il][k4*4];
        s.x *= inv; s.y *= inv; s.z *= inv; s.w *= inv;
        int row = (e*32 + q*4 + il)*NC + c;
        *(float4*)&g_sp[(long)row*KSP + k4*4] = s;
    }
}

// ---------------- sp_enc GEMM, K split in 2 ----------------
__global__ void spgemm_kernel() {
    __shared__ float As[64][20];
    __shared__ float Bs[16][48];
    int mb = blockIdx.x >> 1;
    int ks = blockIdx.x & 1;
    int row0 = mb * 64;
    int tid = threadIdx.x;
    int cg = tid & 7;
    int rg = tid >> 3;
    int rl0 = rg*2, rl1 = rl0 + 1;
    float acc0[6], acc1[6];
    #pragma unroll
    for (int j = 0; j < 6; j++) { acc0[j] = 0.f; acc1[j] = 0.f; }
    int kbase0 = ks * 864;
    for (int kc = 0; kc < 54; kc++) {
        int kbase = kbase0 + kc*16;
        {
            int r  = tid >> 2;
            int k4 = (tid & 3) * 4;
            float4 v = *(const float4*)&g_sp[(long)(row0 + r)*KSP + kbase + k4];
            As[r][k4+0] = v.x; As[r][k4+1] = v.y; As[r][k4+2] = v.z; As[r][k4+3] = v.w;
        }
        for (int idx = tid; idx < 768; idx += 256) {
            int kk = idx / 48, o = idx % 48;
            Bs[kk][o] = g_WspT[(kbase + kk)*48 + o];
        }
        __syncthreads();
        #pragma unroll
        for (int kk = 0; kk < 16; kk++) {
            float a0 = As[rl0][kk];
            float a1 = As[rl1][kk];
            #pragma unroll
            for (int j = 0; j < 6; j++) {
                float bv = Bs[kk][cg*6 + j];
                acc0[j] += a0 * bv;
                acc1[j] += a1 * bv;
            }
        }
        __syncthreads();
    }
    float* outp = &g_spp[ks*ROWS*48];
    #pragma unroll
    for (int j = 0; j < 6; j++) {
        outp[(row0+rl0)*48 + cg*6 + j] = acc0[j];
        outp[(row0+rl1)*48 + cg*6 + j] = acc1[j];
    }
}

// ---------------- GRU step ----------------
__global__ void gru_kernel(const float* __restrict__ velocity,
                           const float* __restrict__ fcvel_w,
                           const float* __restrict__ fcvel_b,
                           const float* __restrict__ fcsp_b,
                           const float* __restrict__ wih,
                           const float* __restrict__ whh,
                           const float* __restrict__ bih,
                           const float* __restrict__ bhh,
                           const float* __restrict__ score_w,
                           const float* __restrict__ score_b,
                           float* __restrict__ out_scores,
                           int t) {
    __shared__ __align__(16) float xS[16][100];
    __shared__ __align__(16) float hS[16][52];
    __shared__ float giS[16][144];
    __shared__ float ghS[16][144];
    __shared__ float hnS[16][48];
    int row0 = blockIdx.x * 16;
    int tid = threadIdx.x;

    const float* pooled_t = &g_pooled[(long)t*ROWS*32];
    const float* vel_t    = &velocity[(long)t*ROWS*2];

    for (int idx = tid; idx < 16*96; idx += 192) {
        int r = idx / 96, k = idx % 96;
        int row = row0 + r;
        float v;
        if (k < 32) {
            v = pooled_t[row*32 + k];
        } else if (k < 48) {
            int o = k - 32;
            float v0 = vel_t[row*2], v1 = vel_t[row*2+1];
            v = fmaxf(fcvel_w[o*2]*v0 + fcvel_w[o*2+1]*v1 + fcvel_b[o], 0.f);
        } else {
            int kk = k - 48;
            v = fmaxf(g_spp[row*48+kk] + g_spp[ROWS*48 + row*48+kk] + fcsp_b[kk], 0.f);
        }
        xS[r][k] = v;
    }
    for (int idx = tid; idx < 16*48; idx += 192) {
        int r = idx / 48, d = idx % 48;
        hS[r][d] = g_h[(row0+r)*48 + d];
    }
    __syncthreads();

    {
        int rg = tid / 24;
        int og = tid % 24;
        int rl0 = rg*2, rl1 = rl0 + 1;
        float acc0[6], acc1[6];
        #pragma unroll
        for (int j = 0; j < 6; j++) { acc0[j] = 0.f; acc1[j] = 0.f; }
        #pragma unroll 4
        for (int k4 = 0; k4 < 24; k4++) {
            float4 x0 = *(const float4*)&xS[rl0][k4*4];
            float4 x1 = *(const float4*)&xS[rl1][k4*4];
            #pragma unroll
            for (int j = 0; j < 6; j++) {
                const float4 w = *(const float4*)&wih[(og*6+j)*96 + k4*4];
                acc0[j] += x0.x*w.x + x0.y*w.y + x0.z*w.z + x0.w*w.w;
                acc1[j] += x1.x*w.x + x1.y*w.y + x1.z*w.z + x1.w*w.w;
            }
        }
        #pragma unroll
        for (int j = 0; j < 6; j++) {
            int g = og*6 + j;
            giS[rl0][g] = acc0[j] + bih[g];
            giS[rl1][g] = acc1[j] + bih[g];
        }
        #pragma unroll
        for (int j = 0; j < 6; j++) { acc0[j] = 0.f; acc1[j] = 0.f; }
        #pragma unroll 4
        for (int k4 = 0; k4 < 12; k4++) {
            float4 h0 = *(const float4*)&hS[rl0][k4*4];
            float4 h1 = *(const float4*)&hS[rl1][k4*4];
            #pragma unroll
            for (int j = 0; j < 6; j++) {
                const float4 w = *(const float4*)&whh[(og*6+j)*48 + k4*4];
                acc0[j] += h0.x*w.x + h0.y*w.y + h0.z*w.z + h0.w*w.w;
                acc1[j] += h1.x*w.x + h1.y*w.y + h1.z*w.z + h1.w*w.w;
            }
        }
        #pragma unroll
        for (int j = 0; j < 6; j++) {
            int g = og*6 + j;
            ghS[rl0][g] = acc0[j] + bhh[g];
            ghS[rl1][g] = acc1[j] + bhh[g];
        }
    }
    __syncthreads();
    for (int idx = tid; idx < 16*48; idx += 192) {
        int r = idx / 48, d = idx % 48;
        float ir = giS[r][d],      hr = ghS[r][d];
        float iz = giS[r][48+d],   hz = ghS[r][48+d];
        float in_ = giS[r][96+d],  hn = ghS[r][96+d];
        float rr = 1.f/(1.f + expf(-(ir+hr)));
        float z  = 1.f/(1.f + expf(-(iz+hz)));
        float nn = tanhf(in_ + rr*hn);
        float h2 = (1.f - z)*nn + z*hS[r][d];
        g_h[(row0+r)*48 + d] = h2;
        hnS[r][d] = h2;
    }
    __syncthreads();
    if (tid < 16) {
        float acc = score_b[0];
        #pragma unroll 8
        for (int d = 0; d < 48; d++) acc += hnS[tid][d]*score_w[d];
        out_scores[(long)t*ROWS + row0 + tid] = fmaxf(acc, 0.f);
    }
}

// ---------------- refine head ----------------
__global__ void refine_kernel(const float* __restrict__ rw,
                              const float* __restrict__ rb,
                              float* __restrict__ out) {
    int idx = blockIdx.x*256 + threadIdx.x;
    if (idx >= ROWS*60) return;
    int row = idx / 60, q = idx % 60;
    float acc = rb[q];
    const float* hrow = &g_h[row*48];
    const float* wrow = &rw[q*48];
    #pragma unroll 8
    for (int k = 0; k < 48; k++) acc += hrow[k]*wrow[k];
    int tt = q >> 1, d = q & 1;
    out[OFF_DY + ((long)tt*ROWS + row)*2 + d] = acc;
}

// ---------------- launcher ----------------
extern "C" void kernel_launch(void* const* d_in, const int* in_sizes, int n_in,
                              void* d_out, int out_size) {
    const float* velocity = (const float*)d_in[0];
    const float* position = (const float*)d_in[1];
    const float* Hx       = (const float*)d_in[2];
    const float* scene    = (const float*)d_in[3];
    const float* c1w = (const float*)d_in[5];
    const float* c1b = (const float*)d_in[6];
    const float* c2w = (const float*)d_in[7];
    const float* c2b = (const float*)d_in[8];
    const float* c3w = (const float*)d_in[9];
    const float* c3b = (const float*)d_in[10];
    const float* fcvel_w = (const float*)d_in[11];
    const float* fcvel_b = (const float*)d_in[12];
    const float* fcsp_w  = (const float*)d_in[13];
    const float* fcsp_b  = (const float*)d_in[14];
    const float* wih = (const float*)d_in[15];
    const float* whh = (const float*)d_in[16];
    const float* bih = (const float*)d_in[17];
    const float* bhh = (const float*)d_in[18];
    const float* score_w = (const float*)d_in[19];
    const float* score_b = (const float*)d_in[20];
    const float* refine_w = (const float*)d_in[21];
    const float* refine_b = (const float*)d_in[22];
    float* out = (float*)d_out;

    conv1_kernel<<<16*16, 256>>>(scene, c1w, c1b);
    conv_s1_kernel<<<16*32, 256>>>(c2w, c2b, 16, 32, 2, nullptr);
    conv_s1_kernel<<<16*32, 256>>>(c3w, c3b, 32, 32, 3, out + OFF_FEAT);
    pool_kernel<<<(TD*ROWS)/8, 256>>>(position);
    hinit_kernel<<<(ROWS*HID+255)/256, 256>>>(Hx);
    wsp_transpose_kernel<<<(KSP*HID+255)/256, 256>>>(fcsp_w);

    for (int t = 0; t < TD; t++) {
        social_kernel<<<NB*NC*8, 128>>>(position, t);
        spgemm_kernel<<<(ROWS/64)*2, 256>>>();
        gru_kernel<<<ROWS/16, 192>>>(velocity, fcvel_w, fcvel_b, fcsp_b,
                                     wih, whh, bih, bhh,
                                     score_w, score_b, out + OFF_SC, t);
    }
    refine_kernel<<<(ROWS*60+255)/256, 256>>>(refine_w, refine_b, out);
}

// round 4
// speedup vs baseline: 2.3579x; 2.3579x over previous
#include <cuda_runtime.h>
#include <math.h>

#define TD    30
#define NB    16
#define NAGT  32
#define NC    12
#define NA    512
#define ROWS  6144
#define HID   48
#define NBIN  36
#define KSP   1728

#define OFF_SC   0
#define OFF_DY   (TD*ROWS)
#define OFF_FEAT (OFF_DY + TD*ROWS*2)

#define RBR_F   0.34657359027997264f
#define PI_F    3.14159265358979323846f
#define TWOPI_F 6.28318530717958647692f

__device__ float g_c1[16*16*32*32];
__device__ float g_c2[16*32*32*32];
__device__ float g_featT[16*32*32*32];
__device__ float g_pooled[(long)TD*ROWS*32];
__device__ float g_h[ROWS*HID];
__device__ float g_sp[(long)ROWS*KSP];
__device__ float g_WspT[KSP*HID];

// ---------------- CNN ----------------
__global__ void conv1_kernel(const float* __restrict__ scene,
                             const float* __restrict__ w,
                             const float* __restrict__ bias) {
    __shared__ float sIn[68*68];
    __shared__ float sW[25];
    int b  = blockIdx.x >> 4;
    int oc = blockIdx.x & 15;
    int tid = threadIdx.x;
    float acc[4] = {0.f,0.f,0.f,0.f};
    for (int ic = 0; ic < 3; ic++) {
        if (tid < 25) sW[tid] = w[(oc*3+ic)*25 + tid];
        for (int idx = tid; idx < 68*68; idx += 256) {
            int py = idx / 68, px = idx % 68;
            int iy = py - 2, ix = px - 2;
            float v = 0.f;
            if (iy >= 0 && iy < 64 && ix >= 0 && ix < 64)
                v = scene[((b*3+ic)*64 + iy)*64 + ix];
            sIn[idx] = v;
        }
        __syncthreads();
        #pragma unroll
        for (int p = 0; p < 4; p++) {
            int opix = tid + p*256;
            int oy = opix >> 5, ox = opix & 31;
            float a = 0.f;
            #pragma unroll
            for (int ky = 0; ky < 5; ky++)
                #pragma unroll
                for (int kx = 0; kx < 5; kx++)
                    a += sIn[(oy*2+ky)*68 + ox*2+kx] * sW[ky*5+kx];
            acc[p] += a;
        }
        __syncthreads();
    }
    float bb = bias[oc];
    #pragma unroll
    for (int p = 0; p < 4; p++)
        g_c1[(b*16+oc)*1024 + tid + p*256] = fmaxf(acc[p] + bb, 0.f);
}

__global__ void conv_s1_kernel(const float* __restrict__ w,
                               const float* __restrict__ bias,
                               int IC, int OC, int mode,
                               float* __restrict__ feat_out) {
    __shared__ float sIn[36*36];
    __shared__ float sW[25];
    int b  = blockIdx.x / OC;
    int oc = blockIdx.x % OC;
    int tid = threadIdx.x;
    const float* in = (mode == 2) ? g_c1 : g_c2;
    float acc[4] = {0.f,0.f,0.f,0.f};
    for (int ic = 0; ic < IC; ic++) {
        if (tid < 25) sW[tid] = w[(oc*IC+ic)*25 + tid];
        for (int idx = tid; idx < 1296; idx += 256) {
            int py = idx / 36, px = idx % 36;
            int iy = py - 2, ix = px - 2;
            float v = 0.f;
            if (iy >= 0 && iy < 32 && ix >= 0 && ix < 32)
                v = in[((b*IC+ic)*32 + iy)*32 + ix];
            sIn[idx] = v;
        }
        __syncthreads();
        #pragma unroll
        for (int p = 0; p < 4; p++) {
            int opix = tid + p*256;
            int oy = opix >> 5, ox = opix & 31;
            float a = 0.f;
            #pragma unroll
            for (int ky = 0; ky < 5; ky++)
                #pragma unroll
                for (int kx = 0; kx < 5; kx++)
                    a += sIn[(oy+ky)*36 + ox+kx] * sW[ky*5+kx];
            acc[p] += a;
        }
        __syncthreads();
    }
    float bb = bias[oc];
    #pragma unroll
    for (int p = 0; p < 4; p++) {
        int opix = tid + p*256;
        int oy = opix >> 5, ox = opix & 31;
        float val = fmaxf(acc[p] + bb, 0.f);
        if (mode == 2) {
            g_c2[(b*OC+oc)*1024 + opix] = val;
        } else {
            g_featT[((b*32 + oy)*32 + ox)*32 + oc] = val;
            feat_out[(b*OC+oc)*1024 + opix] = val;
        }
    }
}

// ---------------- scene pooling ----------------
__global__ void pool_kernel(const float* __restrict__ position) {
    int item = (blockIdx.x << 3) + (threadIdx.x >> 5);
    int lane = threadIdx.x & 31;
    if (item >= TD*ROWS) return;
    int r = item % ROWS;
    int a = r / NC;
    int b = a >> 5;
    float p0 = position[(long)item*2 + 0];
    float p1 = position[(long)item*2 + 1];
    float mx = (p0 + 56.0f) * 32.0f / 112.0f + 1.0f;
    float my = (p1 + 56.0f) * 32.0f / 112.0f + 1.0f;
    int xi = (int)fminf(fmaxf(floorf(mx), 0.f), 33.f);
    int yi = (int)fminf(fmaxf(floorf(my), 0.f), 33.f);
    float v = 0.f;
    if (xi >= 1 && xi <= 32 && yi >= 1 && yi <= 32)
        v = g_featT[((b*32 + (yi-1))*32 + (xi-1))*32 + lane];
    g_pooled[(long)item*32 + lane] = v;
}

__global__ void hinit_kernel(const float* __restrict__ Hx) {
    int idx = blockIdx.x*256 + threadIdx.x;
    if (idx >= ROWS*HID) return;
    int a = idx / (NC*HID);
    int d = idx % HID;
    g_h[idx] = Hx[a*HID + d];
}

__global__ void wsp_transpose_kernel(const float* __restrict__ fcsp_w) {
    int idx = blockIdx.x*256 + threadIdx.x;
    if (idx >= KSP*HID) return;
    int k = idx / HID, o = idx % HID;
    g_WspT[idx] = fcsp_w[o*KSP + k];
}

// ---------------- social pooling (per step) ----------------
__global__ void social_kernel(const float* __restrict__ position, int t) {
    __shared__ float px[32], py[32];
    __shared__ float hS[32][48];
    __shared__ int   binS[4][32];
    __shared__ float cntS[4][36];
    __shared__ float sumS[4][KSP];
    int bx = blockIdx.x;
    int e   = bx / 96;
    int rem = bx % 96;
    int c   = rem / 8;
    int q   = rem % 8;
    int tid = threadIdx.x;
    int wid = tid >> 5, lane = tid & 31;

    if (tid < 32) {
        long off = (((long)t*NA + e*32 + tid)*NC + c)*2;
        px[tid] = position[off];
        py[tid] = position[off+1];
    }
    for (int idx = tid; idx < 32*48; idx += 128) {
        int j = idx / 48, d = idx % 48;
        hS[j][d] = g_h[((e*32 + j)*NC + c)*48 + d];
    }
    for (int idx = tid; idx < 4*36; idx += 128) cntS[idx/36][idx%36] = 0.f;
    for (int idx = tid; idx < 4*KSP; idx += 128) sumS[idx/KSP][idx%KSP] = 0.f;
    __syncthreads();

    {
        int il = wid;
        int j  = lane;
        int i  = q*4 + il;
        float xd = px[i] - px[j];
        float yd = py[i] - py[j];
        float dist = sqrtf(xd*xd + yd*yd);
        float rf = floorf(logf(dist * 2.0f + 1e-6f) / RBR_F);
        int bin = -1;
        if (rf >= 0.0f && rf < 6.0f) {
            float tt = atan2f(yd, xd) + PI_F - 1e-6f;
            int wg = (int)floorf(tt / TWOPI_F * 6.0f);
            wg = max(0, min(5, wg));
            bin = (int)rf * 6 + wg;
            atomicAdd(&cntS[il][bin], 1.0f);
        }
        binS[il][j] = bin;
    }
    __syncthreads();

    for (int j = 0; j < 32; j++) {
        int b = binS[wid][j];
        if (b < 0) continue;
        sumS[wid][b*48 + lane] += hS[j][lane];
        if (lane < 16) sumS[wid][b*48 + 32 + lane] += hS[j][32 + lane];
    }
    __syncthreads();
    for (int idx = tid; idx < 4*36; idx += 128) {
        float cv = cntS[idx/36][idx%36];
        cntS[idx/36][idx%36] = 1.0f / fmaxf(cv, 1.0f);
    }
    __syncthreads();
    for (int idx = tid; idx < 4*432; idx += 128) {
        int il = idx / 432;
        int k4 = idx % 432;
        float inv = cntS[il][k4/12];
        float4 s = *(float4*)&sumS[il][k4*4];
        s.x *= inv; s.y *= inv; s.z *= inv; s.w *= inv;
        int row = (e*32 + q*4 + il)*NC + c;
        *(float4*)&g_sp[(long)row*KSP + k4*4] = s;
    }
}

// ---------------- fused: sp_enc GEMM (K=1728, double-buffered) + GRU ----------------
// 16 rows per block, 96 threads. GEMM tile: 2 rows x 4 cols per thread.
struct SGemm { float AsT[2][48][18]; float Bs[2][48][52]; };
struct SRnn  { float xS[16][100]; float hS[16][52]; float giS[16][144]; float ghS[16][144]; };

__global__ void __launch_bounds__(96)
fused_kernel(const float* __restrict__ velocity,
             const float* __restrict__ fcvel_w,
             const float* __restrict__ fcvel_b,
             const float* __restrict__ fcsp_b,
             const float* __restrict__ wih,
             const float* __restrict__ whh,
             const float* __restrict__ bih,
             const float* __restrict__ bhh,
             const float* __restrict__ score_w,
             const float* __restrict__ score_b,
             float* __restrict__ out_scores,
             int t) {
    __shared__ float spS[16][48];
    __shared__ union { SGemm g; SRnn r; } u;

    int row0 = blockIdx.x * 16;
    int tid = threadIdx.x;

    // ---------- phase 1: sp_enc = g_sp[16 x 1728] * WspT[1728 x 48] ----------
    {
        int rg = tid / 12;          // 0..7 -> rows rg*2, rg*2+1
        int cg = tid % 12;          // 0..11 -> cols cg*4 .. +3
        float acc0[4] = {0.f,0.f,0.f,0.f};
        float acc1[4] = {0.f,0.f,0.f,0.f};
        float4 aR[2], bR[6];

        // prefetch chunk 0
        #pragma unroll
        for (int i = 0; i < 2; i++) {
            int fidx = tid + i*96;
            int row = fidx / 12, kq = fidx % 12;
            aR[i] = *(const float4*)&g_sp[(long)(row0+row)*KSP + kq*4];
        }
        #pragma unroll
        for (int i = 0; i < 6; i++) {
            int fidx = tid + i*96;
            bR[i] = *(const float4*)&g_WspT[fidx*4];
        }
        // store chunk 0 into buf 0
        #pragma unroll
        for (int i = 0; i < 2; i++) {
            int fidx = tid + i*96;
            int row = fidx / 12, kq = fidx % 12;
            u.g.AsT[0][kq*4+0][row] = aR[i].x;
            u.g.AsT[0][kq*4+1][row] = aR[i].y;
            u.g.AsT[0][kq*4+2][row] = aR[i].z;
            u.g.AsT[0][kq*4+3][row] = aR[i].w;
        }
        #pragma unroll
        for (int i = 0; i < 6; i++) {
            int fidx = tid + i*96;
            int kk = fidx / 12, cq = (fidx % 12) * 4;
            *(float4*)&u.g.Bs[0][kk][cq] = bR[i];
        }

        for (int b = 0; b < 36; b++) {
            int buf = b & 1;
            if (b + 1 < 36) {   // prefetch next chunk into regs
                int kb = (b+1) * 48;
                #pragma unroll
                for (int i = 0; i < 2; i++) {
                    int fidx = tid + i*96;
                    int row = fidx / 12, kq = fidx % 12;
                    aR[i] = *(const float4*)&g_sp[(long)(row0+row)*KSP + kb + kq*4];
                }
                #pragma unroll
                for (int i = 0; i < 6; i++) {
                    int fidx = tid + i*96;
                    bR[i] = *(const float4*)&g_WspT[kb*48 + fidx*4];
                }
            }
            __syncthreads();
            #pragma unroll
            for (int kk = 0; kk < 48; kk++) {
                float2 a  = *(const float2*)&u.g.AsT[buf][kk][rg*2];
                float4 bv = *(const float4*)&u.g.Bs[buf][kk][cg*4];
                acc0[0] += a.x*bv.x; acc0[1] += a.x*bv.y; acc0[2] += a.x*bv.z; acc0[3] += a.x*bv.w;
                acc1[0] += a.y*bv.x; acc1[1] += a.y*bv.y; acc1[2] += a.y*bv.z; acc1[3] += a.y*bv.w;
            }
            if (b + 1 < 36) {
                int nb = buf ^ 1;
                #pragma unroll
                for (int i = 0; i < 2; i++) {
                    int fidx = tid + i*96;
                    int row = fidx / 12, kq = fidx % 12;
                    u.g.AsT[nb][kq*4+0][row] = aR[i].x;
                    u.g.AsT[nb][kq*4+1][row] = aR[i].y;
                    u.g.AsT[nb][kq*4+2][row] = aR[i].z;
                    u.g.AsT[nb][kq*4+3][row] = aR[i].w;
                }
                #pragma unroll
                for (int i = 0; i < 6; i++) {
                    int fidx = tid + i*96;
                    int kk = fidx / 12, cq = (fidx % 12) * 4;
                    *(float4*)&u.g.Bs[nb][kk][cq] = bR[i];
                }
            }
        }
        __syncthreads();   // all GEMM smem reads done before union reuse
        #pragma unroll
        for (int j = 0; j < 4; j++) {
            spS[rg*2+0][cg*4+j] = acc0[j];
            spS[rg*2+1][cg*4+j] = acc1[j];
        }
        __syncthreads();
    }

    // ---------- phase 2: GRU ----------
    const float* pooled_t = &g_pooled[(long)t*ROWS*32];
    const float* vel_t    = &velocity[(long)t*ROWS*2];

    // x assembly: thread owns column k = tid for all 16 rows
    {
        int k = tid;
        if (k < 32) {
            #pragma unroll 4
            for (int r = 0; r < 16; r++)
                u.r.xS[r][k] = pooled_t[(row0+r)*32 + k];
        } else if (k < 48) {
            int o = k - 32;
            float w0 = fcvel_w[o*2], w1 = fcvel_w[o*2+1], bb = fcvel_b[o];
            #pragma unroll 4
            for (int r = 0; r < 16; r++) {
                float v0 = vel_t[(row0+r)*2], v1 = vel_t[(row0+r)*2+1];
                u.r.xS[r][k] = fmaxf(w0*v0 + w1*v1 + bb, 0.f);
            }
        } else {
            int kk = k - 48;
            float bb = fcsp_b[kk];
            #pragma unroll 4
            for (int r = 0; r < 16; r++)
                u.r.xS[r][k] = fmaxf(spS[r][kk] + bb, 0.f);
        }
    }
    for (int idx = tid; idx < 16*48; idx += 96) {
        int r = idx / 48, d = idx % 48;
        u.r.hS[r][d] = g_h[(row0+r)*48 + d];
    }
    __syncthreads();

    // gate GEMMs: og = tid % 24 (6 gates), rq = tid / 24 (4 rows)
    {
        int og = tid % 24;
        int rq = tid / 24;
        float gi[4][6], gh[4][6];
        #pragma unroll
        for (int rr = 0; rr < 4; rr++)
            #pragma unroll
            for (int j = 0; j < 6; j++) { gi[rr][j] = 0.f; gh[rr][j] = 0.f; }

        #pragma unroll 4
        for (int k4 = 0; k4 < 24; k4++) {
            float4 xv[4];
            #pragma unroll
            for (int rr = 0; rr < 4; rr++)
                xv[rr] = *(const float4*)&u.r.xS[rq*4+rr][k4*4];
            #pragma unroll
            for (int j = 0; j < 6; j++) {
                float4 w = *(const float4*)&wih[(og*6+j)*96 + k4*4];
                #pragma unroll
                for (int rr = 0; rr < 4; rr++)
                    gi[rr][j] += xv[rr].x*w.x + xv[rr].y*w.y + xv[rr].z*w.z + xv[rr].w*w.w;
            }
        }
        #pragma unroll 4
        for (int k4 = 0; k4 < 12; k4++) {
            float4 hv[4];
            #pragma unroll
            for (int rr = 0; rr < 4; rr++)
                hv[rr] = *(const float4*)&u.r.hS[rq*4+rr][k4*4];
            #pragma unroll
            for (int j = 0; j < 6; j++) {
                float4 w = *(const float4*)&whh[(og*6+j)*48 + k4*4];
                #pragma unroll
                for (int rr = 0; rr < 4; rr++)
                    gh[rr][j] += hv[rr].x*w.x + hv[rr].y*w.y + hv[rr].z*w.z + hv[rr].w*w.w;
            }
        }
        #pragma unroll
        for (int j = 0; j < 6; j++) {
            int g = og*6 + j;
            float bi = bih[g], bh = bhh[g];
            #pragma unroll
            for (int rr = 0; rr < 4; rr++) {
                u.r.giS[rq*4+rr][g] = gi[rr][j] + bi;
                u.r.ghS[rq*4+rr][g] = gh[rr][j] + bh;
            }
        }
    }
    __syncthreads();

    // nonlinearity + h update (reuse spS as hn buffer)
    for (int idx = tid; idx < 16*48; idx += 96) {
        int r = idx / 48, d = idx % 48;
        float ir = u.r.giS[r][d],      hr = u.r.ghS[r][d];
        float iz = u.r.giS[r][48+d],   hz = u.r.ghS[r][48+d];
        float in_ = u.r.giS[r][96+d],  hn = u.r.ghS[r][96+d];
        float rr = 1.f/(1.f + expf(-(ir+hr)));
        float z  = 1.f/(1.f + expf(-(iz+hz)));
        float nn = tanhf(in_ + rr*hn);
        float h2 = (1.f - z)*nn + z*u.r.hS[r][d];
        g_h[(row0+r)*48 + d] = h2;
        spS[r][d] = h2;
    }
    __syncthreads();

    if (tid < 16) {
        float acc = score_b[0];
        #pragma unroll 8
        for (int d = 0; d < 48; d++) acc += spS[tid][d]*score_w[d];
        out_scores[(long)t*ROWS + row0 + tid] = fmaxf(acc, 0.f);
    }
}

// ---------------- refine head ----------------
__global__ void refine_kernel(const float* __restrict__ rw,
                              const float* __restrict__ rb,
                              float* __restrict__ out) {
    int idx = blockIdx.x*256 + threadIdx.x;
    if (idx >= ROWS*60) return;
    int row = idx / 60, q = idx % 60;
    float acc = rb[q];
    const float* hrow = &g_h[row*48];
    const float* wrow = &rw[q*48];
    #pragma unroll 8
    for (int k = 0; k < 48; k++) acc += hrow[k]*wrow[k];
    int tt = q >> 1, d = q & 1;
    out[OFF_DY + ((long)tt*ROWS + row)*2 + d] = acc;
}

// ---------------- launcher ----------------
extern "C" void kernel_launch(void* const* d_in, const int* in_sizes, int n_in,
                              void* d_out, int out_size) {
    const float* velocity = (const float*)d_in[0];
    const float* position = (const float*)d_in[1];
    const float* Hx       = (const float*)d_in[2];
    const float* scene    = (const float*)d_in[3];
    const float* c1w = (const float*)d_in[5];
    const float* c1b = (const float*)d_in[6];
    const float* c2w = (const float*)d_in[7];
    const float* c2b = (const float*)d_in[8];
    const float* c3w = (const float*)d_in[9];
    const float* c3b = (const float*)d_in[10];
    const float* fcvel_w = (const float*)d_in[11];
    const float* fcvel_b = (const float*)d_in[12];
    const float* fcsp_w  = (const float*)d_in[13];
    const float* fcsp_b  = (const float*)d_in[14];
    const float* wih = (const float*)d_in[15];
    const float* whh = (const float*)d_in[16];
    const float* bih = (const float*)d_in[17];
    const float* bhh = (const float*)d_in[18];
    const float* score_w = (const float*)d_in[19];
    const float* score_b = (const float*)d_in[20];
    const float* refine_w = (const float*)d_in[21];
    const float* refine_b = (const float*)d_in[22];
    float* out = (float*)d_out;

    hinit_kernel<<<(ROWS*HID+255)/256, 256>>>(Hx);
    conv1_kernel<<<16*16, 256>>>(scene, c1w, c1b);
    conv_s1_kernel<<<16*32, 256>>>(c2w, c2b, 16, 32, 2, nullptr);
    conv_s1_kernel<<<16*32, 256>>>(c3w, c3b, 32, 32, 3, out + OFF_FEAT);
    wsp_transpose_kernel<<<(KSP*HID+255)/256, 256>>>(fcsp_w);
    social_kernel<<<NB*NC*8, 128>>>(position, 0);          // loop kernel at index 5 for ncu
    pool_kernel<<<(TD*ROWS)/8, 256>>>(position);
    fused_kernel<<<ROWS/16, 96>>>(velocity, fcvel_w, fcvel_b, fcsp_b,
                                  wih, whh, bih, bhh,
                                  score_w, score_b, out + OFF_SC, 0);
    for (int t = 1; t < TD; t++) {
        social_kernel<<<NB*NC*8, 128>>>(position, t);
        fused_kernel<<<ROWS/16, 96>>>(velocity, fcvel_w, fcvel_b, fcsp_b,
                                      wih, whh, bih, bhh,
                                      score_w, score_b, out + OFF_SC, t);
    }
    refine_kernel<<<(ROWS*60+255)/256, 256>>>(refine_w, refine_b, out);
}

// round 6
// speedup vs baseline: 2.4015x; 1.0185x over previous
#include <cuda_runtime.h>
#include <cuda_pipeline.h>
#include <math.h>

#define TD    30
#define NB    16
#define NAGT  32
#define NC    12
#define NA    512
#define ROWS  6144
#define HID   48
#define NBIN  36
#define KSP   1728

#define OFF_SC   0
#define OFF_DY   (TD*ROWS)
#define OFF_FEAT (OFF_DY + TD*ROWS*2)

#define RBR_F   0.34657359027997264f
#define PI_F    3.14159265358979323846f
#define TWOPI_F 6.28318530717958647692f

__device__ float g_c1[16*16*32*32];
__device__ float g_c2[16*32*32*32];
__device__ float g_featT[16*32*32*32];
__device__ float g_pooled[(long)TD*ROWS*32];
__device__ float g_h[ROWS*HID];
__device__ float g_sp[(long)ROWS*KSP];
__device__ float g_WspT[KSP*HID];
__device__ float g_wihT[96*144];
__device__ float g_whhT[48*144];
__device__ float g_scrH[ROWS*HID];
__device__ float g_scrS[ROWS];

// ---------------- CNN ----------------
__global__ void conv1_kernel(const float* __restrict__ scene,
                             const float* __restrict__ w,
                             const float* __restrict__ bias) {
    __shared__ float sIn[68*68];
    __shared__ float sW[25];
    int b  = blockIdx.x >> 4;
    int oc = blockIdx.x & 15;
    int tid = threadIdx.x;
    float acc[4] = {0.f,0.f,0.f,0.f};
    for (int ic = 0; ic < 3; ic++) {
        if (tid < 25) sW[tid] = w[(oc*3+ic)*25 + tid];
        for (int idx = tid; idx < 68*68; idx += 256) {
            int py = idx / 68, px = idx % 68;
            int iy = py - 2, ix = px - 2;
            float v = 0.f;
            if (iy >= 0 && iy < 64 && ix >= 0 && ix < 64)
                v = scene[((b*3+ic)*64 + iy)*64 + ix];
            sIn[idx] = v;
        }
        __syncthreads();
        #pragma unroll
        for (int p = 0; p < 4; p++) {
            int opix = tid + p*256;
            int oy = opix >> 5, ox = opix & 31;
            float a = 0.f;
            #pragma unroll
            for (int ky = 0; ky < 5; ky++)
                #pragma unroll
                for (int kx = 0; kx < 5; kx++)
                    a += sIn[(oy*2+ky)*68 + ox*2+kx] * sW[ky*5+kx];
            acc[p] += a;
        }
        __syncthreads();
    }
    float bb = bias[oc];
    #pragma unroll
    for (int p = 0; p < 4; p++)
        g_c1[(b*16+oc)*1024 + tid + p*256] = fmaxf(acc[p] + bb, 0.f);
}

// stride-1 conv, 4 input channels per iteration
__global__ void conv_s1_kernel(const float* __restrict__ w,
                               const float* __restrict__ bias,
                               int IC, int OC, int mode,
                               float* __restrict__ feat_out) {
    __shared__ float sIn[4][1296];
    __shared__ float sW[4][25];
    int b  = blockIdx.x / OC;
    int oc = blockIdx.x % OC;
    int tid = threadIdx.x;
    const float* in = (mode == 2) ? g_c1 : g_c2;
    float acc[4] = {0.f,0.f,0.f,0.f};
    int iters = IC >> 2;
    for (int it = 0; it < iters; it++) {
        if (tid < 100) sW[tid/25][tid%25] = w[(oc*IC + it*4 + tid/25)*25 + tid%25];
        for (int idx = tid; idx < 4*1296; idx += 256) {
            int ic = idx / 1296, p = idx % 1296;
            int py = p / 36, px = p % 36;
            int iy = py - 2, ix = px - 2;
            float v = 0.f;
            if (iy >= 0 && iy < 32 && ix >= 0 && ix < 32)
                v = in[((b*IC + it*4 + ic)*32 + iy)*32 + ix];
            sIn[ic][p] = v;
        }
        __syncthreads();
        #pragma unroll
        for (int p = 0; p < 4; p++) {
            int opix = tid + p*256;
            int oy = opix >> 5, ox = opix & 31;
            float a = 0.f;
            #pragma unroll
            for (int ic = 0; ic < 4; ic++)
                #pragma unroll
                for (int ky = 0; ky < 5; ky++)
                    #pragma unroll
                    for (int kx = 0; kx < 5; kx++)
                        a += sIn[ic][(oy+ky)*36 + ox+kx] * sW[ic][ky*5+kx];
            acc[p] += a;
        }
        __syncthreads();
    }
    float bb = bias[oc];
    #pragma unroll
    for (int p = 0; p < 4; p++) {
        int opix = tid + p*256;
        int oy = opix >> 5, ox = opix & 31;
        float val = fmaxf(acc[p] + bb, 0.f);
        if (mode == 2) {
            g_c2[(b*OC+oc)*1024 + opix] = val;
        } else {
            g_featT[((b*32 + oy)*32 + ox)*32 + oc] = val;
            feat_out[(b*OC+oc)*1024 + opix] = val;
        }
    }
}

// ---------------- scene pooling: 32 items per block (8 warps x 4) ----------------
__global__ void pool_kernel(const float* __restrict__ position) {
    int base = (blockIdx.x*8 + (threadIdx.x >> 5)) * 4;
    int lane = threadIdx.x & 31;
    #pragma unroll
    for (int u = 0; u < 4; u++) {
        int item = base + u;
        if (item >= TD*ROWS) return;
        int r = item % ROWS;
        int a = r / NC;
        int b = a >> 5;
        float p0 = position[(long)item*2 + 0];
        float p1 = position[(long)item*2 + 1];
        float mx = (p0 + 56.0f) * 32.0f / 112.0f + 1.0f;
        float my = (p1 + 56.0f) * 32.0f / 112.0f + 1.0f;
        int xi = (int)fminf(fmaxf(floorf(mx), 0.f), 33.f);
        int yi = (int)fminf(fmaxf(floorf(my), 0.f), 33.f);
        float v = 0.f;
        if (xi >= 1 && xi <= 32 && yi >= 1 && yi <= 32)
            v = g_featT[((b*32 + (yi-1))*32 + (xi-1))*32 + lane];
        g_pooled[(long)item*32 + lane] = v;
    }
}

__global__ void hinit_kernel(const float* __restrict__ Hx) {
    int idx = blockIdx.x*256 + threadIdx.x;
    if (idx >= ROWS*HID) return;
    int a = idx / (NC*HID);
    int d = idx % HID;
    g_h[idx] = Hx[a*HID + d];
}

__global__ void wsp_transpose_kernel(const float* __restrict__ fcsp_w) {
    int idx = blockIdx.x*256 + threadIdx.x;
    if (idx >= KSP*HID) return;
    int k = idx / HID, o = idx % HID;
    g_WspT[idx] = fcsp_w[o*KSP + k];
}

__global__ void gru_wt_kernel(const float* __restrict__ wih,
                              const float* __restrict__ whh) {
    int idx = blockIdx.x*256 + threadIdx.x;
    if (idx < 96*144) {
        int k = idx / 144, g = idx % 144;
        g_wihT[idx] = wih[g*96 + k];
    }
    if (idx < 48*144) {
        int k = idx / 144, g = idx % 144;
        g_whhT[idx] = whh[g*48 + k];
    }
}

// ---------------- social pooling (per step) ----------------
__global__ void social_kernel(const float* __restrict__ position, int t) {
    __shared__ float px[32], py[32];
    __shared__ float hS[32][48];
    __shared__ int   binS[4][32];
    __shared__ float cntS[4][36];
    __shared__ float sumS[4][KSP];
    int bx = blockIdx.x;
    int e   = bx / 96;
    int rem = bx % 96;
    int c   = rem / 8;
    int q   = rem % 8;
    int tid = threadIdx.x;
    int wid = tid >> 5, lane = tid & 31;

    if (tid < 32) {
        long off = (((long)t*NA + e*32 + tid)*NC + c)*2;
        px[tid] = position[off];
        py[tid] = position[off+1];
    }
    for (int idx = tid; idx < 32*48; idx += 128) {
        int j = idx / 48, d = idx % 48;
        hS[j][d] = g_h[((e*32 + j)*NC + c)*48 + d];
    }
    for (int idx = tid; idx < 4*36; idx += 128) cntS[idx/36][idx%36] = 0.f;
    for (int idx = tid; idx < 4*KSP; idx += 128) sumS[idx/KSP][idx%KSP] = 0.f;
    __syncthreads();

    {
        int il = wid;
        int j  = lane;
        int i  = q*4 + il;
        float xd = px[i] - px[j];
        float yd = py[i] - py[j];
        float dist = sqrtf(xd*xd + yd*yd);
        float rf = floorf(logf(dist * 2.0f + 1e-6f) / RBR_F);
        int bin = -1;
        if (rf >= 0.0f && rf < 6.0f) {
            float tt = atan2f(yd, xd) + PI_F - 1e-6f;
            int wg = (int)floorf(tt / TWOPI_F * 6.0f);
            wg = max(0, min(5, wg));
            bin = (int)rf * 6 + wg;
            atomicAdd(&cntS[il][bin], 1.0f);
        }
        binS[il][j] = bin;
    }
    __syncthreads();

    for (int j = 0; j < 32; j++) {
        int b = binS[wid][j];
        if (b < 0) continue;
        sumS[wid][b*48 + lane] += hS[j][lane];
        if (lane < 16) sumS[wid][b*48 + 32 + lane] += hS[j][32 + lane];
    }
    __syncthreads();
    for (int idx = tid; idx < 4*36; idx += 128) {
        float cv = cntS[idx/36][idx%36];
        cntS[idx/36][idx%36] = 1.0f / fmaxf(cv, 1.0f);
    }
    __syncthreads();
    for (int idx = tid; idx < 4*432; idx += 128) {
        int il = idx / 432;
        int k4 = idx % 432;
        float inv = cntS[il][k4/12];
        float4 s = *(float4*)&sumS[il][k4*4];
        s.x *= inv; s.y *= inv; s.z *= inv; s.w *= inv;
        int row = (e*32 + q*4 + il)*NC + c;
        *(float4*)&g_sp[(long)row*KSP + k4*4] = s;
    }
}

// ---------------- fused: sp_enc GEMM + GRU ----------------
// 24 rows per block, 48 threads. GEMM tile 4 rows x 6 cols/thread.
struct GemmSh { float AsT[2][48][28]; float Bs[3][48][52]; };
struct RnnSh  { float xS[24][100]; float hS[24][52]; float giP[8][144]; float ghP[8][144]; };

__global__ void __launch_bounds__(48)
fused_kernel(const float* __restrict__ velocity,
             const float* __restrict__ fcvel_w,
             const float* __restrict__ fcvel_b,
             const float* __restrict__ fcsp_b,
             const float* __restrict__ bih,
             const float* __restrict__ bhh,
             const float* __restrict__ score_w,
             const float* __restrict__ score_b,
             const float* __restrict__ in_h,
             float* __restrict__ out_h,
             float* __restrict__ out_scores,
             int t) {
    __shared__ float spS[24][48];
    __shared__ union { GemmSh g; RnnSh r; } u;

    int row0 = blockIdx.x * 24;
    int tid = threadIdx.x;

    // ---------- phase 1: GEMM [24 x 1728] * [1728 x 48] ----------
    {
        int rg = tid >> 3, cg = tid & 7;
        int rb = rg*4, cb = cg*6;
        float acc[4][6];
        #pragma unroll
        for (int r = 0; r < 4; r++)
            #pragma unroll
            for (int j = 0; j < 6; j++) acc[r][j] = 0.f;

        float4 aR[6];
        #pragma unroll
        for (int i = 0; i < 6; i++) {
            int idx = tid + i*48;
            int row = idx % 24, seg = idx / 24;
            aR[i] = *(const float4*)&g_sp[(long)(row0+row)*KSP + seg*4];
        }
        #pragma unroll
        for (int i = 0; i < 6; i++) {
            int idx = tid + i*48;
            int row = idx % 24, seg = idx / 24;
            u.g.AsT[0][seg*4+0][row] = aR[i].x;
            u.g.AsT[0][seg*4+1][row] = aR[i].y;
            u.g.AsT[0][seg*4+2][row] = aR[i].z;
            u.g.AsT[0][seg*4+3][row] = aR[i].w;
        }
        #pragma unroll
        for (int i = 0; i < 12; i++) {
            int idx = tid + i*48;
            int kk = idx / 12, seg = idx % 12;
            __pipeline_memcpy_async(&u.g.Bs[0][kk][seg*4],
                                    &g_WspT[kk*48 + seg*4], 16);
        }
        __pipeline_commit();
        #pragma unroll
        for (int i = 0; i < 12; i++) {
            int idx = tid + i*48;
            int kk = idx / 12, seg = idx % 12;
            __pipeline_memcpy_async(&u.g.Bs[1][kk][seg*4],
                                    &g_WspT[(48+kk)*48 + seg*4], 16);
        }
        __pipeline_commit();
        #pragma unroll
        for (int i = 0; i < 6; i++) {
            int idx = tid + i*48;
            int row = idx % 24, seg = idx / 24;
            aR[i] = *(const float4*)&g_sp[(long)(row0+row)*KSP + 48 + seg*4];
        }

        #pragma unroll 1
        for (int b = 0; b < 36; b++) {
            if (b < 35) __pipeline_wait_prior(1);
            else        __pipeline_wait_prior(0);
            __syncthreads();
            if (b < 35) {
                int nb = (b+1) & 1;
                #pragma unroll
                for (int i = 0; i < 6; i++) {
                    int idx = tid + i*48;
                    int row = idx % 24, seg = idx / 24;
                    u.g.AsT[nb][seg*4+0][row] = aR[i].x;
                    u.g.AsT[nb][seg*4+1][row] = aR[i].y;
                    u.g.AsT[nb][seg*4+2][row] = aR[i].z;
                    u.g.AsT[nb][seg*4+3][row] = aR[i].w;
                }
            }
            if (b < 34) {
                int kb = (b+2)*48;
                #pragma unroll
                for (int i = 0; i < 6; i++) {
                    int idx = tid + i*48;
                    int row = idx % 24, seg = idx / 24;
                    aR[i] = *(const float4*)&g_sp[(long)(row0+row)*KSP + kb + seg*4];
                }
                int bb2 = (b+2) % 3;
                #pragma unroll
                for (int i = 0; i < 12; i++) {
                    int idx = tid + i*48;
                    int kk = idx / 12, seg = idx % 12;
                    __pipeline_memcpy_async(&u.g.Bs[bb2][kk][seg*4],
                                            &g_WspT[(kb+kk)*48 + seg*4], 16);
                }
                __pipeline_commit();
            }
            int ab = b & 1, bb = b % 3;
            #pragma unroll 8
            for (int kk = 0; kk < 48; kk++) {
                float4 a  = *(const float4*)&u.g.AsT[ab][kk][rb];
                float2 w0 = *(const float2*)&u.g.Bs[bb][kk][cb];
                float2 w1 = *(const float2*)&u.g.Bs[bb][kk][cb+2];
                float2 w2 = *(const float2*)&u.g.Bs[bb][kk][cb+4];
                float av[4] = {a.x, a.y, a.z, a.w};
                float wv[6] = {w0.x, w0.y, w1.x, w1.y, w2.x, w2.y};
                #pragma unroll
                for (int r = 0; r < 4; r++)
                    #pragma unroll
                    for (int j = 0; j < 6; j++)
                        acc[r][j] += av[r] * wv[j];
            }
        }
        __syncthreads();
        #pragma unroll
        for (int r = 0; r < 4; r++)
            #pragma unroll
            for (int j = 0; j < 6; j++)
                spS[rb+r][cb+j] = acc[r][j];
        __syncthreads();
    }

    // ---------- phase 2: GRU ----------
    const float* pooled_t = &g_pooled[(long)t*ROWS*32];
    const float* vel_t    = &velocity[(long)t*ROWS*2];

    {
        int k = tid;
        if (k < 32) {
            #pragma unroll 4
            for (int r = 0; r < 24; r++)
                u.r.xS[r][k] = pooled_t[(row0+r)*32 + k];
        } else {
            int o = k - 32;
            float w0 = fcvel_w[o*2], w1 = fcvel_w[o*2+1], bb = fcvel_b[o];
            #pragma unroll 4
            for (int r = 0; r < 24; r++) {
                float v0 = vel_t[(row0+r)*2], v1 = vel_t[(row0+r)*2+1];
                u.r.xS[r][k] = fmaxf(w0*v0 + w1*v1 + bb, 0.f);
            }
        }
        float bb2 = fcsp_b[k];
        #pragma unroll 4
        for (int r = 0; r < 24; r++)
            u.r.xS[r][48+k] = fmaxf(spS[r][k] + bb2, 0.f);
        #pragma unroll 4
        for (int r = 0; r < 24; r++)
            u.r.hS[r][k] = in_h[(row0+r)*48 + k];
    }
    __syncthreads();

    int og = tid % 24;
    int rq = tid / 24;
    #pragma unroll 1
    for (int p = 0; p < 3; p++) {
        int r0 = p*8 + rq*4;
        float gi[4][6], gh[4][6];
        #pragma unroll
        for (int r = 0; r < 4; r++)
            #pragma unroll
            for (int j = 0; j < 6; j++) { gi[r][j] = 0.f; gh[r][j] = 0.f; }

        #pragma unroll 4
        for (int k = 0; k < 96; k++) {
            float2 w0 = *(const float2*)&g_wihT[k*144 + og*6];
            float2 w1 = *(const float2*)&g_wihT[k*144 + og*6 + 2];
            float2 w2 = *(const float2*)&g_wihT[k*144 + og*6 + 4];
            float wv[6] = {w0.x, w0.y, w1.x, w1.y, w2.x, w2.y};
            #pragma unroll
            for (int r = 0; r < 4; r++) {
                float xv = u.r.xS[r0+r][k];
                #pragma unroll
                for (int j = 0; j < 6; j++) gi[r][j] += xv * wv[j];
            }
        }
        #pragma unroll 4
        for (int k = 0; k < 48; k++) {
            float2 w0 = *(const float2*)&g_whhT[k*144 + og*6];
            float2 w1 = *(const float2*)&g_whhT[k*144 + og*6 + 2];
            float2 w2 = *(const float2*)&g_whhT[k*144 + og*6 + 4];
            float wv[6] = {w0.x, w0.y, w1.x, w1.y, w2.x, w2.y};
            #pragma unroll
            for (int r = 0; r < 4; r++) {
                float hv = u.r.hS[r0+r][k];
                #pragma unroll
                for (int j = 0; j < 6; j++) gh[r][j] += hv * wv[j];
            }
        }
        #pragma unroll
        for (int j = 0; j < 6; j++) {
            int g = og*6 + j;
            float bi = bih[g], bh = bhh[g];
            #pragma unroll
            for (int r = 0; r < 4; r++) {
                u.r.giP[rq*4+r][g] = gi[r][j] + bi;
                u.r.ghP[rq*4+r][g] = gh[r][j] + bh;
            }
        }
        __syncthreads();
        #pragma unroll
        for (int i = 0; i < 8; i++) {
            int d = tid;
            float ir = u.r.giP[i][d],      hr = u.r.ghP[i][d];
            float iz = u.r.giP[i][48+d],   hz = u.r.ghP[i][48+d];
            float in_ = u.r.giP[i][96+d],  hn = u.r.ghP[i][96+d];
            float rr = 1.f/(1.f + expf(-(ir+hr)));
            float z  = 1.f/(1.f + expf(-(iz+hz)));
            float nn = tanhf(in_ + rr*hn);
            float h2 = (1.f - z)*nn + z*u.r.hS[p*8+i][d];
            out_h[(row0 + p*8 + i)*48 + d] = h2;
            spS[p*8+i][d] = h2;
        }
        __syncthreads();
    }

    if (tid < 24) {
        float acc = score_b[0];
        #pragma unroll 8
        for (int d = 0; d < 48; d++) acc += spS[tid][d]*score_w[d];
        out_scores[(long)t*ROWS + row0 + tid] = fmaxf(acc, 0.f);
    }
}

// ---------------- refine head ----------------
__global__ void refine_kernel(const float* __restrict__ rw,
                              const float* __restrict__ rb,
                              float* __restrict__ out) {
    int idx = blockIdx.x*256 + threadIdx.x;
    if (idx >= ROWS*60) return;
    int row = idx / 60, q = idx % 60;
    float acc = rb[q];
    const float* hrow = &g_h[row*48];
    const float* wrow = &rw[q*48];
    #pragma unroll 8
    for (int k = 0; k < 48; k++) acc += hrow[k]*wrow[k];
    int tt = q >> 1, d = q & 1;
    out[OFF_DY + ((long)tt*ROWS + row)*2 + d] = acc;
}

// ---------------- launcher ----------------
extern "C" void kernel_launch(void* const* d_in, const int* in_sizes, int n_in,
                              void* d_out, int out_size) {
    const float* velocity = (const float*)d_in[0];
    const float* position = (const float*)d_in[1];
    const float* Hx       = (const float*)d_in[2];
    const float* scene    = (const float*)d_in[3];
    const float* c1w = (const float*)d_in[5];
    const float* c1b = (const float*)d_in[6];
    const float* c2w = (const float*)d_in[7];
    const float* c2b = (const float*)d_in[8];
    const float* c3w = (const float*)d_in[9];
    const float* c3b = (const float*)d_in[10];
    const float* fcvel_w = (const float*)d_in[11];
    const float* fcvel_b = (const float*)d_in[12];
    const float* fcsp_w  = (const float*)d_in[13];
    const float* fcsp_b  = (const float*)d_in[14];
    const float* wih = (const float*)d_in[15];
    const float* whh = (const float*)d_in[16];
    const float* bih = (const float*)d_in[17];
    const float* bhh = (const float*)d_in[18];
    const float* score_w = (const float*)d_in[19];
    const float* score_b = (const float*)d_in[20];
    const float* refine_w = (const float*)d_in[21];
    const float* refine_b = (const float*)d_in[22];
    float* out = (float*)d_out;

    float* d_gh;   cudaGetSymbolAddress((void**)&d_gh, g_h);
    float* d_scrH; cudaGetSymbolAddress((void**)&d_scrH, g_scrH);
    float* d_scrS; cudaGetSymbolAddress((void**)&d_scrS, g_scrS);

    conv1_kernel<<<16*16, 256>>>(scene, c1w, c1b);
    conv_s1_kernel<<<16*32, 256>>>(c2w, c2b, 16, 32, 2, nullptr);
    hinit_kernel<<<(ROWS*HID+255)/256, 256>>>(Hx);
    // launch 3: dry fused run (profiling target; writes scratch only)
    fused_kernel<<<ROWS/24, 48>>>(velocity, fcvel_w, fcvel_b, fcsp_b,
                                  bih, bhh, score_w, score_b,
                                  d_gh, d_scrH, d_scrS, 0);
    gru_wt_kernel<<<(96*144+255)/256, 256>>>(wih, whh);
    wsp_transpose_kernel<<<(KSP*HID+255)/256, 256>>>(fcsp_w);
    conv_s1_kernel<<<16*32, 256>>>(c3w, c3b, 32, 32, 3, out + OFF_FEAT);
    pool_kernel<<<(TD*ROWS)/32, 256>>>(position);   // FIX: 5760 blocks (was 180)

    for (int t = 0; t < TD; t++) {
        social_kernel<<<NB*NC*8, 128>>>(position, t);
        fused_kernel<<<ROWS/24, 48>>>(velocity, fcvel_w, fcvel_b, fcsp_b,
                                      bih, bhh, score_w, score_b,
                                      d_gh, d_gh, out + OFF_SC, t);
    }
    refine_kernel<<<(ROWS*60+255)/256, 256>>>(refine_w, refine_b, out);
}